// round 10
// baseline (speedup 1.0000x reference)
#include <cuda_runtime.h>
#include <cstdint>

#define B_   16
#define Q_   900
#define C_   91
#define T_   100
#define BT_  1600
#define BQ_  14400
#define COST_ELEMS 23040000
#define RPB  8
#define CT   256

// smem layout for cost kernel (R6-identical)
#define OFF_TB   0                       // float4[1600] cxcywh
#define OFF_XY   25600                   // float4[1600] xyxy
#define OFF_TA   51200                   // float [1600] area
#define OFF_TL   57600                   // int   [1600] labels
#define OFF_PR   64000                   // float [RPB][92] sigmoid probs
#define SMEM_COST (OFF_PR + RPB * 92 * 4)

// Per-(batch, col<100) running minima, stored INVERTED (~packed) so that
// atomicMax over zero-initialized memory is correct on the first run and
// idempotent across graph replays. packed = (fkey<<32)|(local_row<<7)|col.
__device__ unsigned long long g_colmax[B_][128];        // zero-initialized

// Transposed mirror of the first 100 columns of each batch's cost block:
// g_costT[b][col][row]. Deterministically fully overwritten by every
// cost_kernel run -> no init required. Makes greedy rescans coalesced.
__device__ float g_costT[B_][T_][Q_];

__device__ __forceinline__ unsigned fkey(float f) {
    unsigned b = __float_as_uint(f);
    return (b & 0x80000000u) ? ~b : (b | 0x80000000u);
}

// ---------------------------------------------------------------------------
// Kernel 1: cost matrix [BQ_, BT_] — hot loop identical to R6/R8, plus fused
// per-column min tracking and transposed store for cols < 100.
// ---------------------------------------------------------------------------
__global__ __launch_bounds__(CT)
void cost_kernel(const float* __restrict__ logits,
                 const float* __restrict__ pred_boxes,
                 const int*   __restrict__ tgt_labels,
                 const float* __restrict__ tgt_boxes,
                 float* __restrict__ out)
{
    extern __shared__ char dyn[];
    float4* s_tb = (float4*)(dyn + OFF_TB);
    float4* s_xy = (float4*)(dyn + OFF_XY);
    float*  s_ta = (float*) (dyn + OFF_TA);
    int*    s_tl = (int*)   (dyn + OFF_TL);
    float*  s_pr = (float*) (dyn + OFF_PR);   // [RPB][92]

    const int tid = threadIdx.x;
    const int base_i = blockIdx.x * RPB;

    const float4* tb4 = reinterpret_cast<const float4*>(tgt_boxes);
    for (int j = tid; j < BT_; j += CT) {
        float4 t = tb4[j];
        s_tb[j] = t;
        float x0 = t.x - 0.5f * t.z, y0 = t.y - 0.5f * t.w;
        float x1 = t.x + 0.5f * t.z, y1 = t.y + 0.5f * t.w;
        s_xy[j] = make_float4(x0, y0, x1, y1);
        s_ta[j] = (x1 - x0) * (y1 - y0);
        s_tl[j] = tgt_labels[j];
    }
    for (int k = tid; k < RPB * C_; k += CT) {
        int rr = k / C_, c = k % C_;
        float x = logits[(size_t)(base_i + rr) * C_ + c];
        s_pr[rr * 92 + c] = 1.0f / (1.0f + expf(-x));
    }
    __syncthreads();

    // register-resident row constants
    float pcx[RPB], pcy[RPB], pw[RPB], ph[RPB];
    float px0[RPB], py0[RPB], px1[RPB], py1[RPB], pa[RPB];
    #pragma unroll
    for (int rr = 0; rr < RPB; rr++) {
        float4 pb = reinterpret_cast<const float4*>(pred_boxes)[base_i + rr];
        pcx[rr] = pb.x; pcy[rr] = pb.y; pw[rr] = pb.z; ph[rr] = pb.w;
        px0[rr] = pb.x - 0.5f * pb.z; py0[rr] = pb.y - 0.5f * pb.w;
        px1[rr] = pb.x + 0.5f * pb.z; py1[rr] = pb.y + 0.5f * pb.w;
        pa[rr]  = (px1[rr] - px0[rr]) * (py1[rr] - py0[rr]);
    }
    float* orow0 = out + (size_t)base_i * BT_;

    // batch-straddle split: rr < split -> batch bb0, else bb0+1
    const int bb0   = base_i / Q_;
    const int split = min(RPB, (bb0 + 1) * Q_ - base_i);
    const int lr0   = base_i - bb0 * Q_;

    for (int j = tid; j < BT_; j += CT) {
        float4 t = s_tb[j];
        float4 x = s_xy[j];
        float ta = s_ta[j];
        int lb = s_tl[j];
        const bool track = (j < T_);
        unsigned long long m_lo = ~0ull, m_hi = ~0ull;

        #pragma unroll
        for (int rr = 0; rr < RPB; rr++) {
            float l1 = fabsf(pcx[rr] - t.x) + fabsf(pcy[rr] - t.y)
                     + fabsf(pw[rr] - t.z) + fabsf(ph[rr] - t.w);
            float ltx = fmaxf(px0[rr], x.x), lty = fmaxf(py0[rr], x.y);
            float rbx = fminf(px1[rr], x.z), rby = fminf(py1[rr], x.w);
            float inter = fmaxf(rbx - ltx, 0.0f) * fmaxf(rby - lty, 0.0f);
            float uni = pa[rr] + ta - inter;
            float iou = inter / uni;
            float ex0 = fminf(px0[rr], x.x), ey0 = fminf(py0[rr], x.y);
            float ex1 = fmaxf(px1[rr], x.z), ey1 = fmaxf(py1[rr], x.w);
            float earea = (ex1 - ex0) * (ey1 - ey0);
            float giou = iou - (earea - uni) / earea;
            float cv = l1 - s_pr[rr * 92 + lb] - giou;
            orow0[(size_t)rr * BT_ + j] = cv;

            if (track) {
                int bbr  = (rr < split) ? bb0 : bb0 + 1;
                int lrow = (rr < split) ? (lr0 + rr) : (rr - split);
                g_costT[bbr][j][lrow] = cv;              // transposed mirror
                unsigned long long p =
                    ((unsigned long long)fkey(cv) << 32)
                    | (unsigned)((lrow << 7) | j);
                if (rr < split) { if (p < m_lo) m_lo = p; }
                else            { if (p < m_hi) m_hi = p; }
            }
        }
        if (track) {
            atomicMax(&g_colmax[bb0][j], ~m_lo);
            if (split < RPB) atomicMax(&g_colmax[bb0 + 1][j], ~m_hi);
        }
    }
}

// ---------------------------------------------------------------------------
// Kernel 2: greedy matcher, one warp per batch, state in registers.
// Rescans read the TRANSPOSED mirror -> 29 coalesced lines, MLP=29.
// ---------------------------------------------------------------------------
__device__ __forceinline__ unsigned redux_min_u32(unsigned v) {
    unsigned d;
    asm("redux.sync.min.u32 %0, %1, 0xffffffff;" : "=r"(d) : "r"(v));
    return d;
}

#define FULLM 0xFFFFFFFFu
#define NITER 29   // ceil(900/32)

__global__ __launch_bounds__(32)
void greedy_kernel(float* __restrict__ rows_out,
                   float* __restrict__ cols_out)
{
    const int b = blockIdx.x;
    const int lane = threadIdx.x;

    // un-invert: unwritten entries (0) become ~0ull = +inf sentinel
    unsigned long long slot[4];
    #pragma unroll
    for (int s = 0; s < 4; s++)
        slot[s] = (lane < 25) ? ~g_colmax[b][lane * 4 + s] : ~0ull;
    unsigned mrow = 0;

    float* ro = rows_out + b * T_;
    float* co = cols_out + b * T_;

    for (int step = 0; step < T_; step++) {
        unsigned long long m = slot[0];
        if (slot[1] < m) m = slot[1];
        if (slot[2] < m) m = slot[2];
        if (slot[3] < m) m = slot[3];

        unsigned k  = (unsigned)(m >> 32);
        unsigned mk = redux_min_u32(k);
        unsigned tag = (k == mk) ? (unsigned)m : 0xFFFFFFFFu;
        unsigned mt  = redux_min_u32(tag);

        const int r = (int)(mt >> 7);
        const int c = (int)(mt & 0x7Fu);

        if (lane == 0) { ro[step] = (float)r; co[step] = (float)c; }
        if (lane == (r & 31)) mrow |= 1u << (r >> 5);
        if (lane == (c >> 2)) slot[c & 3] = ~0ull;   // remove matched column

        if (step == T_ - 1) break;

        // columns whose cached min row was just matched need a rescan
        bool n0 = ((int)((slot[0] >> 7) & 0x3FFu) == r);
        bool n1 = ((int)((slot[1] >> 7) & 0x3FFu) == r);
        bool n2 = ((int)((slot[2] >> 7) & 0x3FFu) == r);
        bool n3 = ((int)((slot[3] >> 7) & 0x3FFu) == r);
        unsigned any = __ballot_sync(FULLM, n0 | n1 | n2 | n3);
        if (any == 0) continue;   // common case

        #pragma unroll
        for (int s = 0; s < 4; s++) {
            bool ns = (s == 0) ? n0 : (s == 1) ? n1 : (s == 2) ? n2 : n3;
            unsigned need = __ballot_sync(FULLM, ns);
            while (need) {
                int ln = __ffs(need) - 1;
                need &= need - 1;
                int cc = __shfl_sync(FULLM, (int)(slot[s] & 0x7Fu), ln);
                const float* colp = g_costT[b][cc];       // contiguous column!
                unsigned long long best = ~0ull;
                #pragma unroll
                for (int i = 0; i < NITER; i++) {
                    int rr = lane + 32 * i;
                    float v = (rr < Q_) ? colp[rr] : 0.0f;  // coalesced
                    if (rr < Q_ && !((mrow >> i) & 1u)) {
                        unsigned long long p =
                            ((unsigned long long)fkey(v) << 32)
                            | (unsigned)((rr << 7) | cc);
                        if (p < best) best = p;
                    }
                }
                unsigned bk  = (unsigned)(best >> 32);
                unsigned mbk = redux_min_u32(bk);
                unsigned bt  = (bk == mbk) ? (unsigned)best : 0xFFFFFFFFu;
                unsigned mbt = redux_min_u32(bt);
                if (lane == ln)
                    slot[s] = ((unsigned long long)mbk << 32) | mbt;
            }
        }
    }
}

// ---------------------------------------------------------------------------
extern "C" void kernel_launch(void* const* d_in, const int* in_sizes, int n_in,
                              void* d_out, int out_size)
{
    const float* logits     = (const float*)d_in[0];
    const float* pred_boxes = (const float*)d_in[1];
    const int*   tgt_labels = (const int*)  d_in[2];
    const float* tgt_boxes  = (const float*)d_in[3];
    float* out = (float*)d_out;

    cudaFuncSetAttribute(cost_kernel,
                         cudaFuncAttributeMaxDynamicSharedMemorySize, SMEM_COST);

    cost_kernel<<<BQ_ / RPB, CT, SMEM_COST>>>(
        logits, pred_boxes, tgt_labels, tgt_boxes, out);

    greedy_kernel<<<B_, 32>>>(
        out + COST_ELEMS, out + COST_ELEMS + B_ * T_);
}

// round 12
// speedup vs baseline: 1.4131x; 1.4131x over previous
#include <cuda_runtime.h>
#include <cstdint>

#define B_   16
#define Q_   900
#define C_   91
#define T_   100
#define BT_  1600
#define BQ_  14400
#define COST_ELEMS 23040000
#define RPB  8
#define CT   256

// smem layout for cost kernel (R6-identical)
#define OFF_TB   0                       // float4[1600] cxcywh
#define OFF_XY   25600                   // float4[1600] xyxy
#define OFF_TA   51200                   // float [1600] area
#define OFF_TL   57600                   // int   [1600] labels
#define OFF_PR   64000                   // float [RPB][92] sigmoid probs
#define SMEM_COST (OFF_PR + RPB * 92 * 4)

// Per-(batch, col<100) running minima, stored INVERTED (~packed) so that
// atomicMax over zero-initialized memory is correct on the first run and
// idempotent across graph replays. packed = (fkey<<32)|(local_row<<7)|col.
__device__ unsigned long long g_colmax[B_][128];        // zero-initialized

// Transposed mirror of the first 100 columns of each batch's cost block:
// g_costT[b][col][row]. Deterministically fully overwritten by every
// cost_kernel run -> no init required. Makes greedy rescans coalesced.
__device__ float g_costT[B_][T_][Q_];

__device__ __forceinline__ unsigned fkey(float f) {
    unsigned b = __float_as_uint(f);
    return (b & 0x80000000u) ? ~b : (b | 0x80000000u);
}

// ---------------------------------------------------------------------------
// Kernel 1: cost matrix [BQ_, BT_] — hot loop identical to R6/R8, plus fused
// per-column min tracking and transposed store for cols < 100.
// (This exact kernel measured ~93us in R10.)
// ---------------------------------------------------------------------------
__global__ __launch_bounds__(CT)
void cost_kernel(const float* __restrict__ logits,
                 const float* __restrict__ pred_boxes,
                 const int*   __restrict__ tgt_labels,
                 const float* __restrict__ tgt_boxes,
                 float* __restrict__ out)
{
    extern __shared__ char dyn[];
    float4* s_tb = (float4*)(dyn + OFF_TB);
    float4* s_xy = (float4*)(dyn + OFF_XY);
    float*  s_ta = (float*) (dyn + OFF_TA);
    int*    s_tl = (int*)   (dyn + OFF_TL);
    float*  s_pr = (float*) (dyn + OFF_PR);   // [RPB][92]

    const int tid = threadIdx.x;
    const int base_i = blockIdx.x * RPB;

    const float4* tb4 = reinterpret_cast<const float4*>(tgt_boxes);
    for (int j = tid; j < BT_; j += CT) {
        float4 t = tb4[j];
        s_tb[j] = t;
        float x0 = t.x - 0.5f * t.z, y0 = t.y - 0.5f * t.w;
        float x1 = t.x + 0.5f * t.z, y1 = t.y + 0.5f * t.w;
        s_xy[j] = make_float4(x0, y0, x1, y1);
        s_ta[j] = (x1 - x0) * (y1 - y0);
        s_tl[j] = tgt_labels[j];
    }
    for (int k = tid; k < RPB * C_; k += CT) {
        int rr = k / C_, c = k % C_;
        float x = logits[(size_t)(base_i + rr) * C_ + c];
        s_pr[rr * 92 + c] = 1.0f / (1.0f + expf(-x));
    }
    __syncthreads();

    // register-resident row constants
    float pcx[RPB], pcy[RPB], pw[RPB], ph[RPB];
    float px0[RPB], py0[RPB], px1[RPB], py1[RPB], pa[RPB];
    #pragma unroll
    for (int rr = 0; rr < RPB; rr++) {
        float4 pb = reinterpret_cast<const float4*>(pred_boxes)[base_i + rr];
        pcx[rr] = pb.x; pcy[rr] = pb.y; pw[rr] = pb.z; ph[rr] = pb.w;
        px0[rr] = pb.x - 0.5f * pb.z; py0[rr] = pb.y - 0.5f * pb.w;
        px1[rr] = pb.x + 0.5f * pb.z; py1[rr] = pb.y + 0.5f * pb.w;
        pa[rr]  = (px1[rr] - px0[rr]) * (py1[rr] - py0[rr]);
    }
    float* orow0 = out + (size_t)base_i * BT_;

    // batch-straddle split: rr < split -> batch bb0, else bb0+1
    const int bb0   = base_i / Q_;
    const int split = min(RPB, (bb0 + 1) * Q_ - base_i);
    const int lr0   = base_i - bb0 * Q_;

    for (int j = tid; j < BT_; j += CT) {
        float4 t = s_tb[j];
        float4 x = s_xy[j];
        float ta = s_ta[j];
        int lb = s_tl[j];
        const bool track = (j < T_);
        unsigned long long m_lo = ~0ull, m_hi = ~0ull;

        #pragma unroll
        for (int rr = 0; rr < RPB; rr++) {
            float l1 = fabsf(pcx[rr] - t.x) + fabsf(pcy[rr] - t.y)
                     + fabsf(pw[rr] - t.z) + fabsf(ph[rr] - t.w);
            float ltx = fmaxf(px0[rr], x.x), lty = fmaxf(py0[rr], x.y);
            float rbx = fminf(px1[rr], x.z), rby = fminf(py1[rr], x.w);
            float inter = fmaxf(rbx - ltx, 0.0f) * fmaxf(rby - lty, 0.0f);
            float uni = pa[rr] + ta - inter;
            float iou = inter / uni;
            float ex0 = fminf(px0[rr], x.x), ey0 = fminf(py0[rr], x.y);
            float ex1 = fmaxf(px1[rr], x.z), ey1 = fmaxf(py1[rr], x.w);
            float earea = (ex1 - ex0) * (ey1 - ey0);
            float giou = iou - (earea - uni) / earea;
            float cv = l1 - s_pr[rr * 92 + lb] - giou;
            orow0[(size_t)rr * BT_ + j] = cv;

            if (track) {
                int bbr  = (rr < split) ? bb0 : bb0 + 1;
                int lrow = (rr < split) ? (lr0 + rr) : (rr - split);
                g_costT[bbr][j][lrow] = cv;              // transposed mirror
                unsigned long long p =
                    ((unsigned long long)fkey(cv) << 32)
                    | (unsigned)((lrow << 7) | j);
                if (rr < split) { if (p < m_lo) m_lo = p; }
                else            { if (p < m_hi) m_hi = p; }
            }
        }
        if (track) {
            atomicMax(&g_colmax[bb0][j], ~m_lo);
            if (split < RPB) atomicMax(&g_colmax[bb0 + 1][j], ~m_hi);
        }
    }
}

// ---------------------------------------------------------------------------
// Kernel 2: greedy matcher — EXACT R8 structure (rolled rescan loop, load
// guarded by the row mask). Only change vs R8: rescan reads the contiguous
// transposed mirror (colp[rr]) instead of the strided cost column.
// ---------------------------------------------------------------------------
__device__ __forceinline__ unsigned redux_min_u32(unsigned v) {
    unsigned d;
    asm("redux.sync.min.u32 %0, %1, 0xffffffff;" : "=r"(d) : "r"(v));
    return d;
}

#define FULLM 0xFFFFFFFFu

__global__ __launch_bounds__(32)
void greedy_kernel(float* __restrict__ rows_out,
                   float* __restrict__ cols_out)
{
    const int b = blockIdx.x;
    const int lane = threadIdx.x;

    // un-invert: unwritten entries (0) become ~0ull = +inf sentinel
    unsigned long long slot[4];
    #pragma unroll
    for (int s = 0; s < 4; s++)
        slot[s] = (lane < 25) ? ~g_colmax[b][lane * 4 + s] : ~0ull;
    unsigned mrow = 0;

    float* ro = rows_out + b * T_;
    float* co = cols_out + b * T_;

    for (int step = 0; step < T_; step++) {
        unsigned long long m = slot[0];
        if (slot[1] < m) m = slot[1];
        if (slot[2] < m) m = slot[2];
        if (slot[3] < m) m = slot[3];

        unsigned k  = (unsigned)(m >> 32);
        unsigned mk = redux_min_u32(k);
        unsigned tag = (k == mk) ? (unsigned)m : 0xFFFFFFFFu;
        unsigned mt  = redux_min_u32(tag);

        const int r = (int)(mt >> 7);
        const int c = (int)(mt & 0x7Fu);

        if (lane == 0) { ro[step] = (float)r; co[step] = (float)c; }
        if (lane == (r & 31)) mrow |= 1u << (r >> 5);
        if (lane == (c >> 2)) slot[c & 3] = ~0ull;   // remove matched column

        if (step == T_ - 1) break;

        // columns whose cached min row was just matched need a rescan
        bool n0 = ((int)((slot[0] >> 7) & 0x3FFu) == r);
        bool n1 = ((int)((slot[1] >> 7) & 0x3FFu) == r);
        bool n2 = ((int)((slot[2] >> 7) & 0x3FFu) == r);
        bool n3 = ((int)((slot[3] >> 7) & 0x3FFu) == r);
        unsigned any = __ballot_sync(FULLM, n0 | n1 | n2 | n3);
        if (any == 0) continue;   // common case

        #pragma unroll
        for (int s = 0; s < 4; s++) {
            bool ns = (s == 0) ? n0 : (s == 1) ? n1 : (s == 2) ? n2 : n3;
            unsigned need = __ballot_sync(FULLM, ns);
            while (need) {
                int ln = __ffs(need) - 1;
                need &= need - 1;
                int cc = __shfl_sync(FULLM, (int)(slot[s] & 0x7Fu), ln);
                const float* colp = g_costT[b][cc];   // contiguous column
                unsigned long long best = ~0ull;
                for (int i = 0, rr = lane; rr < Q_; i++, rr += 32) {
                    if (!((mrow >> i) & 1u)) {
                        unsigned long long p =
                            ((unsigned long long)fkey(colp[rr]) << 32)
                            | (unsigned)((rr << 7) | cc);
                        if (p < best) best = p;
                    }
                }
                unsigned bk  = (unsigned)(best >> 32);
                unsigned mbk = redux_min_u32(bk);
                unsigned bt  = (bk == mbk) ? (unsigned)best : 0xFFFFFFFFu;
                unsigned mbt = redux_min_u32(bt);
                if (lane == ln)
                    slot[s] = ((unsigned long long)mbk << 32) | mbt;
            }
        }
    }
}

// ---------------------------------------------------------------------------
extern "C" void kernel_launch(void* const* d_in, const int* in_sizes, int n_in,
                              void* d_out, int out_size)
{
    const float* logits     = (const float*)d_in[0];
    const float* pred_boxes = (const float*)d_in[1];
    const int*   tgt_labels = (const int*)  d_in[2];
    const float* tgt_boxes  = (const float*)d_in[3];
    float* out = (float*)d_out;

    cudaFuncSetAttribute(cost_kernel,
                         cudaFuncAttributeMaxDynamicSharedMemorySize, SMEM_COST);

    cost_kernel<<<BQ_ / RPB, CT, SMEM_COST>>>(
        logits, pred_boxes, tgt_labels, tgt_boxes, out);

    greedy_kernel<<<B_, 32>>>(
        out + COST_ELEMS, out + COST_ELEMS + B_ * T_);
}

// round 13
// speedup vs baseline: 1.9227x; 1.3606x over previous
#include <cuda_runtime.h>
#include <cstdint>

#define B_   16
#define Q_   900
#define C_   91
#define T_   100
#define BT_  1600
#define BQ_  14400
#define COST_ELEMS 23040000
#define RPB  8
#define CT   256

#define NB_A 57                 // ceil(14400/256) tracked-column blocks
#define NB_G 16                 // greedy blocks (one per batch)
#define NB_B 1800               // BQ_/RPB full-matrix blocks
#define GRID (NB_A + NB_G + NB_B)

// dynamic smem layout for the B (cost-matrix) role
#define OFF_TB   0                       // float4[1600] cxcywh
#define OFF_XY   25600                   // float4[1600] xyxy
#define OFF_TA   51200                   // float [1600] area
#define OFF_TL   57600                   // int   [1600] labels
#define OFF_PR   64000                   // float [RPB][92] sigmoid probs
#define SMEM_COST (OFF_PR + RPB * 92 * 4)

// Transposed mirror of cols<100: g_costT[b][col][row]. Fully overwritten by
// the A role every run -> no init needed. Contiguous columns for greedy.
__device__ float g_costT[B_][T_][Q_];
// readiness counter (A arrives) + greedy completion counter (self-reset)
__device__ unsigned g_ready;    // zero-init; reset by last greedy block
__device__ unsigned g_done;     // zero-init; reset by last greedy block

__device__ __forceinline__ unsigned fkey(float f) {
    unsigned b = __float_as_uint(f);
    return (b & 0x80000000u) ? ~b : (b | 0x80000000u);
}
__device__ __forceinline__ unsigned redux_min_u32(unsigned v) {
    unsigned d;
    asm("redux.sync.min.u32 %0, %1, 0xffffffff;" : "=r"(d) : "r"(v));
    return d;
}
#define FULLM 0xFFFFFFFFu

// ---------------------------------------------------------------------------
__global__ __launch_bounds__(CT, 3)
void mega_kernel(const float* __restrict__ logits,
                 const float* __restrict__ pred_boxes,
                 const int*   __restrict__ tgt_labels,
                 const float* __restrict__ tgt_boxes,
                 float* __restrict__ out)
{
    extern __shared__ char dyn[];
    const int tid = threadIdx.x;
    const int bid = blockIdx.x;
    const int lane = tid & 31;
    const int wid = tid >> 5;
    const float4* tb4 = reinterpret_cast<const float4*>(tgt_boxes);

    // =================== ROLE A: tracked columns (cols < 100) ==============
    if (bid < NB_A) {
        __shared__ float4 a_tb[T_];
        __shared__ int    a_tl[T_];
        if (tid < T_) { a_tb[tid] = tb4[tid]; a_tl[tid] = tgt_labels[tid]; }
        __syncthreads();

        const int gr = bid * CT + tid;          // global query row
        if (gr < BQ_) {
            float4 pb = reinterpret_cast<const float4*>(pred_boxes)[gr];
            const float pcx = pb.x, pcy = pb.y, pw = pb.z, ph = pb.w;
            const float px0 = pcx - 0.5f * pw, py0 = pcy - 0.5f * ph;
            const float px1 = pcx + 0.5f * pw, py1 = pcy + 0.5f * ph;
            const float pa  = (px1 - px0) * (py1 - py0);
            const int b    = gr / Q_;
            const int lrow = gr - b * Q_;
            const float* lrl = logits + (size_t)gr * C_;

            for (int j = 0; j < T_; j++) {
                float4 t = a_tb[j];
                // identical expressions to the B role (bit-exact)
                float xx0 = t.x - 0.5f * t.z, yy0 = t.y - 0.5f * t.w;
                float xx1 = t.x + 0.5f * t.z, yy1 = t.y + 0.5f * t.w;
                float ta  = (xx1 - xx0) * (yy1 - yy0);
                float pr  = 1.0f / (1.0f + expf(-lrl[a_tl[j]]));

                float l1 = fabsf(pcx - t.x) + fabsf(pcy - t.y)
                         + fabsf(pw - t.z) + fabsf(ph - t.w);
                float ltx = fmaxf(px0, xx0), lty = fmaxf(py0, yy0);
                float rbx = fminf(px1, xx1), rby = fminf(py1, yy1);
                float inter = fmaxf(rbx - ltx, 0.0f) * fmaxf(rby - lty, 0.0f);
                float uni = pa + ta - inter;
                float iou = inter / uni;
                float ex0 = fminf(px0, xx0), ey0 = fminf(py0, yy0);
                float ex1 = fmaxf(px1, xx1), ey1 = fmaxf(py1, yy1);
                float earea = (ex1 - ex0) * (ey1 - ey0);
                float giou = iou - (earea - uni) / earea;
                g_costT[b][j][lrow] = l1 - pr - giou;   // coalesced per warp
            }
        }
        __threadfence();
        __syncthreads();
        if (tid == 0) atomicAdd(&g_ready, 1u);
        return;
    }

    // =================== ROLE G: greedy matcher =============================
    if (bid < NB_A + NB_G) {
        const int b = bid - NB_A;
        // wait for all A blocks (device-scope)
        while (*((volatile unsigned*)&g_ready) < NB_A) __nanosleep(200);
        __threadfence();

        // 8-warp cooperative init of the 100 column minima from g_costT
        __shared__ unsigned long long s_init[T_];
        for (int c = wid; c < T_; c += 8) {
            const float* colp = g_costT[b][c];
            unsigned long long best = ~0ull;
            for (int rr = lane; rr < Q_; rr += 32) {
                unsigned long long p =
                    ((unsigned long long)fkey(colp[rr]) << 32)
                    | (unsigned)((rr << 7) | c);
                if (p < best) best = p;
            }
            unsigned bk  = (unsigned)(best >> 32);
            unsigned mbk = redux_min_u32(bk);
            unsigned bt  = (bk == mbk) ? (unsigned)best : 0xFFFFFFFFu;
            unsigned mbt = redux_min_u32(bt);
            if (lane == 0)
                s_init[c] = ((unsigned long long)mbk << 32) | mbt;
        }
        __syncthreads();
        if (wid != 0) return;

        unsigned long long slot[4];
        #pragma unroll
        for (int s = 0; s < 4; s++)
            slot[s] = (lane < 25) ? s_init[lane * 4 + s] : ~0ull;
        unsigned mrow = 0;

        float* ro = out + COST_ELEMS + b * T_;
        float* co = out + COST_ELEMS + B_ * T_ + b * T_;

        for (int step = 0; step < T_; step++) {
            unsigned long long m = slot[0];
            if (slot[1] < m) m = slot[1];
            if (slot[2] < m) m = slot[2];
            if (slot[3] < m) m = slot[3];

            unsigned k  = (unsigned)(m >> 32);
            unsigned mk = redux_min_u32(k);
            unsigned tag = (k == mk) ? (unsigned)m : 0xFFFFFFFFu;
            unsigned mt  = redux_min_u32(tag);

            const int r = (int)(mt >> 7);
            const int c = (int)(mt & 0x7Fu);

            if (lane == 0) { ro[step] = (float)r; co[step] = (float)c; }
            if (lane == (r & 31)) mrow |= 1u << (r >> 5);
            if (lane == (c >> 2)) slot[c & 3] = ~0ull;

            if (step == T_ - 1) break;

            bool n0 = ((int)((slot[0] >> 7) & 0x3FFu) == r);
            bool n1 = ((int)((slot[1] >> 7) & 0x3FFu) == r);
            bool n2 = ((int)((slot[2] >> 7) & 0x3FFu) == r);
            bool n3 = ((int)((slot[3] >> 7) & 0x3FFu) == r);
            unsigned any = __ballot_sync(FULLM, n0 | n1 | n2 | n3);
            if (any == 0) continue;

            #pragma unroll
            for (int s = 0; s < 4; s++) {
                bool ns = (s == 0) ? n0 : (s == 1) ? n1 : (s == 2) ? n2 : n3;
                unsigned need = __ballot_sync(FULLM, ns);
                while (need) {
                    int ln = __ffs(need) - 1;
                    need &= need - 1;
                    int cc = __shfl_sync(FULLM, (int)(slot[s] & 0x7Fu), ln);
                    const float* colp = g_costT[b][cc];
                    unsigned long long best = ~0ull;
                    for (int i = 0, rr = lane; rr < Q_; i++, rr += 32) {
                        if (!((mrow >> i) & 1u)) {
                            unsigned long long p =
                                ((unsigned long long)fkey(colp[rr]) << 32)
                                | (unsigned)((rr << 7) | cc);
                            if (p < best) best = p;
                        }
                    }
                    unsigned bk  = (unsigned)(best >> 32);
                    unsigned mbk = redux_min_u32(bk);
                    unsigned bt  = (bk == mbk) ? (unsigned)best : 0xFFFFFFFFu;
                    unsigned mbt = redux_min_u32(bt);
                    if (lane == ln)
                        slot[s] = ((unsigned long long)mbk << 32) | mbt;
                }
            }
        }

        // self-reset counters for the next graph replay
        if (lane == 0) {
            __threadfence();
            unsigned old = atomicAdd(&g_done, 1u);
            if (old == NB_G - 1) {
                *((volatile unsigned*)&g_ready) = 0u;
                *((volatile unsigned*)&g_done)  = 0u;
            }
        }
        return;
    }

    // =================== ROLE B: full cost matrix (R12 hot loop) ============
    {
        float4* s_tb = (float4*)(dyn + OFF_TB);
        float4* s_xy = (float4*)(dyn + OFF_XY);
        float*  s_ta = (float*) (dyn + OFF_TA);
        int*    s_tl = (int*)   (dyn + OFF_TL);
        float*  s_pr = (float*) (dyn + OFF_PR);   // [RPB][92]

        const int base_i = (bid - NB_A - NB_G) * RPB;

        for (int j = tid; j < BT_; j += CT) {
            float4 t = tb4[j];
            s_tb[j] = t;
            float x0 = t.x - 0.5f * t.z, y0 = t.y - 0.5f * t.w;
            float x1 = t.x + 0.5f * t.z, y1 = t.y + 0.5f * t.w;
            s_xy[j] = make_float4(x0, y0, x1, y1);
            s_ta[j] = (x1 - x0) * (y1 - y0);
            s_tl[j] = tgt_labels[j];
        }
        for (int k = tid; k < RPB * C_; k += CT) {
            int rr = k / C_, c = k % C_;
            float x = logits[(size_t)(base_i + rr) * C_ + c];
            s_pr[rr * 92 + c] = 1.0f / (1.0f + expf(-x));
        }
        __syncthreads();

        float pcx[RPB], pcy[RPB], pw[RPB], ph[RPB];
        float px0[RPB], py0[RPB], px1[RPB], py1[RPB], pa[RPB];
        #pragma unroll
        for (int rr = 0; rr < RPB; rr++) {
            float4 pb = reinterpret_cast<const float4*>(pred_boxes)[base_i + rr];
            pcx[rr] = pb.x; pcy[rr] = pb.y; pw[rr] = pb.z; ph[rr] = pb.w;
            px0[rr] = pb.x - 0.5f * pb.z; py0[rr] = pb.y - 0.5f * pb.w;
            px1[rr] = pb.x + 0.5f * pb.z; py1[rr] = pb.y + 0.5f * pb.w;
            pa[rr]  = (px1[rr] - px0[rr]) * (py1[rr] - py0[rr]);
        }
        float* orow0 = out + (size_t)base_i * BT_;

        for (int j = tid; j < BT_; j += CT) {
            float4 t = s_tb[j];
            float4 x = s_xy[j];
            float ta = s_ta[j];
            int lb = s_tl[j];
            #pragma unroll
            for (int rr = 0; rr < RPB; rr++) {
                float l1 = fabsf(pcx[rr] - t.x) + fabsf(pcy[rr] - t.y)
                         + fabsf(pw[rr] - t.z) + fabsf(ph[rr] - t.w);
                float ltx = fmaxf(px0[rr], x.x), lty = fmaxf(py0[rr], x.y);
                float rbx = fminf(px1[rr], x.z), rby = fminf(py1[rr], x.w);
                float inter = fmaxf(rbx - ltx, 0.0f) * fmaxf(rby - lty, 0.0f);
                float uni = pa[rr] + ta - inter;
                float iou = inter / uni;
                float ex0 = fminf(px0[rr], x.x), ey0 = fminf(py0[rr], x.y);
                float ex1 = fmaxf(px1[rr], x.z), ey1 = fmaxf(py1[rr], x.w);
                float earea = (ex1 - ex0) * (ey1 - ey0);
                float giou = iou - (earea - uni) / earea;
                orow0[(size_t)rr * BT_ + j] = l1 - s_pr[rr * 92 + lb] - giou;
            }
        }
    }
}

// ---------------------------------------------------------------------------
extern "C" void kernel_launch(void* const* d_in, const int* in_sizes, int n_in,
                              void* d_out, int out_size)
{
    const float* logits     = (const float*)d_in[0];
    const float* pred_boxes = (const float*)d_in[1];
    const int*   tgt_labels = (const int*)  d_in[2];
    const float* tgt_boxes  = (const float*)d_in[3];
    float* out = (float*)d_out;

    cudaFuncSetAttribute(mega_kernel,
                         cudaFuncAttributeMaxDynamicSharedMemorySize, SMEM_COST);

    mega_kernel<<<GRID, CT, SMEM_COST>>>(
        logits, pred_boxes, tgt_labels, tgt_boxes, out);
}

// round 14
// speedup vs baseline: 1.9736x; 1.0264x over previous
#include <cuda_runtime.h>
#include <cstdint>

#define B_   16
#define Q_   900
#define C_   91
#define T_   100
#define BT_  1600
#define BQ_  14400
#define COST_ELEMS 23040000
#define RPB  4
#define CT   256
#define TILES (BQ_ / RPB)        // 3600

#define NB_A 57                  // tracked-column blocks (one row/thread)
#define NB_G 16                  // greedy blocks (one per batch)
#define NB_B 519                 // persistent cost blocks
#define GRID (NB_A + NB_G + NB_B)

// dynamic smem layout (B role)
#define OFF_TB 0                         // float4[1600] target cxcywh
#define OFF_TL 25600                     // uchar[1600] labels
#define OFF_PR 27232                     // float[RPB][92] sigmoid probs
#define SMEM_DYN (OFF_PR + RPB * 92 * 4) // ~28.7 KB -> smem allows >=4 CTAs/SM

// Transposed tracked columns: g_costT[b][col][row]; fully overwritten by A
// every run (no init needed). Contiguous columns for greedy reads.
__device__ float g_costT[B_][T_][Q_];
__device__ unsigned g_ready;    // zero-init; self-reset by last greedy block
__device__ unsigned g_done;     // zero-init; self-reset by last greedy block

__device__ __forceinline__ unsigned fkey(float f) {
    unsigned b = __float_as_uint(f);
    return (b & 0x80000000u) ? ~b : (b | 0x80000000u);
}
__device__ __forceinline__ unsigned redux_min_u32(unsigned v) {
    unsigned d;
    asm("redux.sync.min.u32 %0, %1, 0xffffffff;" : "=r"(d) : "r"(v));
    return d;
}
#define FULLM 0xFFFFFFFFu

// ---------------------------------------------------------------------------
__global__ __launch_bounds__(CT, 4)
void mega_kernel(const float* __restrict__ logits,
                 const float* __restrict__ pred_boxes,
                 const int*   __restrict__ tgt_labels,
                 const float* __restrict__ tgt_boxes,
                 float* __restrict__ out)
{
    extern __shared__ char dyn[];
    const int tid = threadIdx.x;
    const int bid = blockIdx.x;
    const int lane = tid & 31;
    const int wid = tid >> 5;
    const float4* tb4 = reinterpret_cast<const float4*>(tgt_boxes);

    // =================== ROLE A: tracked columns (cols < 100) ==============
    if (bid < NB_A) {
        __shared__ float4 a_tb[T_];
        __shared__ int    a_tl[T_];
        if (tid < T_) { a_tb[tid] = tb4[tid]; a_tl[tid] = tgt_labels[tid]; }
        __syncthreads();

        const int gr = bid * CT + tid;          // global query row
        if (gr < BQ_) {
            float4 pb = reinterpret_cast<const float4*>(pred_boxes)[gr];
            const float pcx = pb.x, pcy = pb.y, pw = pb.z, ph = pb.w;
            const float px0 = pcx - 0.5f * pw, py0 = pcy - 0.5f * ph;
            const float px1 = pcx + 0.5f * pw, py1 = pcy + 0.5f * ph;
            const float pa  = (px1 - px0) * (py1 - py0);
            const int b    = gr / Q_;
            const int lrow = gr - b * Q_;
            const float* lrl = logits + (size_t)gr * C_;

            for (int j = 0; j < T_; j++) {
                float4 t = a_tb[j];
                float xx0 = t.x - 0.5f * t.z, yy0 = t.y - 0.5f * t.w;
                float xx1 = t.x + 0.5f * t.z, yy1 = t.y + 0.5f * t.w;
                float ta  = (xx1 - xx0) * (yy1 - yy0);
                float pr  = 1.0f / (1.0f + expf(-lrl[a_tl[j]]));

                float l1 = fabsf(pcx - t.x) + fabsf(pcy - t.y)
                         + fabsf(pw - t.z) + fabsf(ph - t.w);
                float ltx = fmaxf(px0, xx0), lty = fmaxf(py0, yy0);
                float rbx = fminf(px1, xx1), rby = fminf(py1, yy1);
                float inter = fmaxf(rbx - ltx, 0.0f) * fmaxf(rby - lty, 0.0f);
                float uni = pa + ta - inter;
                float iou = inter / uni;
                float ex0 = fminf(px0, xx0), ey0 = fminf(py0, yy0);
                float ex1 = fmaxf(px1, xx1), ey1 = fmaxf(py1, yy1);
                float earea = (ex1 - ex0) * (ey1 - ey0);
                float giou = iou - (earea - uni) / earea;
                g_costT[b][j][lrow] = l1 - pr - giou;
            }
        }
        __threadfence();
        __syncthreads();
        if (tid == 0) atomicAdd(&g_ready, 1u);
        return;
    }

    // =================== ROLE G: greedy matcher =============================
    if (bid < NB_A + NB_G) {
        const int b = bid - NB_A;
        while (*((volatile unsigned*)&g_ready) < NB_A) __nanosleep(200);
        __threadfence();

        __shared__ unsigned long long s_init[T_];
        for (int c = wid; c < T_; c += 8) {
            const float* colp = g_costT[b][c];
            unsigned long long best = ~0ull;
            for (int rr = lane; rr < Q_; rr += 32) {
                unsigned long long p =
                    ((unsigned long long)fkey(colp[rr]) << 32)
                    | (unsigned)((rr << 7) | c);
                if (p < best) best = p;
            }
            unsigned bk  = (unsigned)(best >> 32);
            unsigned mbk = redux_min_u32(bk);
            unsigned bt  = (bk == mbk) ? (unsigned)best : 0xFFFFFFFFu;
            unsigned mbt = redux_min_u32(bt);
            if (lane == 0)
                s_init[c] = ((unsigned long long)mbk << 32) | mbt;
        }
        __syncthreads();
        if (wid != 0) return;

        unsigned long long slot[4];
        #pragma unroll
        for (int s = 0; s < 4; s++)
            slot[s] = (lane < 25) ? s_init[lane * 4 + s] : ~0ull;
        unsigned mrow = 0;

        float* ro = out + COST_ELEMS + b * T_;
        float* co = out + COST_ELEMS + B_ * T_ + b * T_;

        for (int step = 0; step < T_; step++) {
            unsigned long long m = slot[0];
            if (slot[1] < m) m = slot[1];
            if (slot[2] < m) m = slot[2];
            if (slot[3] < m) m = slot[3];

            unsigned k  = (unsigned)(m >> 32);
            unsigned mk = redux_min_u32(k);
            unsigned tag = (k == mk) ? (unsigned)m : 0xFFFFFFFFu;
            unsigned mt  = redux_min_u32(tag);

            const int r = (int)(mt >> 7);
            const int c = (int)(mt & 0x7Fu);

            if (lane == 0) { ro[step] = (float)r; co[step] = (float)c; }
            if (lane == (r & 31)) mrow |= 1u << (r >> 5);
            if (lane == (c >> 2)) slot[c & 3] = ~0ull;

            if (step == T_ - 1) break;

            bool n0 = ((int)((slot[0] >> 7) & 0x3FFu) == r);
            bool n1 = ((int)((slot[1] >> 7) & 0x3FFu) == r);
            bool n2 = ((int)((slot[2] >> 7) & 0x3FFu) == r);
            bool n3 = ((int)((slot[3] >> 7) & 0x3FFu) == r);
            unsigned any = __ballot_sync(FULLM, n0 | n1 | n2 | n3);
            if (any == 0) continue;

            #pragma unroll
            for (int s = 0; s < 4; s++) {
                bool ns = (s == 0) ? n0 : (s == 1) ? n1 : (s == 2) ? n2 : n3;
                unsigned need = __ballot_sync(FULLM, ns);
                while (need) {
                    int ln = __ffs(need) - 1;
                    need &= need - 1;
                    int cc = __shfl_sync(FULLM, (int)(slot[s] & 0x7Fu), ln);
                    const float* colp = g_costT[b][cc];
                    unsigned long long best = ~0ull;
                    for (int i = 0, rr = lane; rr < Q_; i++, rr += 32) {
                        if (!((mrow >> i) & 1u)) {
                            unsigned long long p =
                                ((unsigned long long)fkey(colp[rr]) << 32)
                                | (unsigned)((rr << 7) | cc);
                            if (p < best) best = p;
                        }
                    }
                    unsigned bk  = (unsigned)(best >> 32);
                    unsigned mbk = redux_min_u32(bk);
                    unsigned bt  = (bk == mbk) ? (unsigned)best : 0xFFFFFFFFu;
                    unsigned mbt = redux_min_u32(bt);
                    if (lane == ln)
                        slot[s] = ((unsigned long long)mbk << 32) | mbt;
                }
            }
        }

        if (lane == 0) {
            __threadfence();
            unsigned old = atomicAdd(&g_done, 1u);
            if (old == NB_G - 1) {
                *((volatile unsigned*)&g_ready) = 0u;
                *((volatile unsigned*)&g_done)  = 0u;
            }
        }
        return;
    }

    // ========= ROLE B: full cost matrix, persistent, RPB=4, 4 CTAs/SM ======
    {
        float4*        s_tb = (float4*)(dyn + OFF_TB);
        unsigned char* s_tl = (unsigned char*)(dyn + OFF_TL);
        float*         s_pr = (float*)(dyn + OFF_PR);   // [RPB][92]

        // stage targets ONCE per persistent block
        for (int j = tid; j < BT_; j += CT) {
            s_tb[j] = tb4[j];
            s_tl[j] = (unsigned char)tgt_labels[j];
        }

        for (int tile = bid - NB_A - NB_G; tile < TILES; tile += NB_B) {
            const int base_i = tile * RPB;
            __syncthreads();   // prior tile readers done (covers target staging on iter 0)
            for (int k = tid; k < RPB * C_; k += CT) {
                int rr = k / C_, c = k % C_;
                float xv = logits[(size_t)(base_i + rr) * C_ + c];
                s_pr[rr * 92 + c] = 1.0f / (1.0f + expf(-xv));
            }
            __syncthreads();

            float pcx[RPB], pcy[RPB], pw[RPB], ph[RPB];
            float px0[RPB], py0[RPB], px1[RPB], py1[RPB], pa[RPB];
            #pragma unroll
            for (int rr = 0; rr < RPB; rr++) {
                float4 pb = reinterpret_cast<const float4*>(pred_boxes)[base_i + rr];
                pcx[rr] = pb.x; pcy[rr] = pb.y; pw[rr] = pb.z; ph[rr] = pb.w;
                px0[rr] = pb.x - 0.5f * pb.z; py0[rr] = pb.y - 0.5f * pb.w;
                px1[rr] = pb.x + 0.5f * pb.z; py1[rr] = pb.y + 0.5f * pb.w;
                pa[rr]  = (px1[rr] - px0[rr]) * (py1[rr] - py0[rr]);
            }
            float* orow0 = out + (size_t)base_i * BT_;

            for (int j = tid; j < BT_; j += CT) {
                float4 t = s_tb[j];
                int lb = s_tl[j];
                float xx0 = t.x - 0.5f * t.z, yy0 = t.y - 0.5f * t.w;
                float xx1 = t.x + 0.5f * t.z, yy1 = t.y + 0.5f * t.w;
                float ta  = (xx1 - xx0) * (yy1 - yy0);
                #pragma unroll
                for (int rr = 0; rr < RPB; rr++) {
                    float l1 = fabsf(pcx[rr] - t.x) + fabsf(pcy[rr] - t.y)
                             + fabsf(pw[rr] - t.z) + fabsf(ph[rr] - t.w);
                    float ltx = fmaxf(px0[rr], xx0), lty = fmaxf(py0[rr], yy0);
                    float rbx = fminf(px1[rr], xx1), rby = fminf(py1[rr], yy1);
                    float inter = fmaxf(rbx - ltx, 0.0f) * fmaxf(rby - lty, 0.0f);
                    float uni = pa[rr] + ta - inter;
                    float iou = inter / uni;
                    float ex0 = fminf(px0[rr], xx0), ey0 = fminf(py0[rr], yy0);
                    float ex1 = fmaxf(px1[rr], xx1), ey1 = fmaxf(py1[rr], yy1);
                    float earea = (ex1 - ex0) * (ey1 - ey0);
                    float giou = iou - (earea - uni) / earea;
                    orow0[(size_t)rr * BT_ + j] = l1 - s_pr[rr * 92 + lb] - giou;
                }
            }
        }
    }
}

// ---------------------------------------------------------------------------
extern "C" void kernel_launch(void* const* d_in, const int* in_sizes, int n_in,
                              void* d_out, int out_size)
{
    const float* logits     = (const float*)d_in[0];
    const float* pred_boxes = (const float*)d_in[1];
    const int*   tgt_labels = (const int*)  d_in[2];
    const float* tgt_boxes  = (const float*)d_in[3];
    float* out = (float*)d_out;

    cudaFuncSetAttribute(mega_kernel,
                         cudaFuncAttributeMaxDynamicSharedMemorySize, SMEM_DYN);

    mega_kernel<<<GRID, CT, SMEM_DYN>>>(
        logits, pred_boxes, tgt_labels, tgt_boxes, out);
}